// round 10
// baseline (speedup 1.0000x reference)
#include <cuda_runtime.h>

#define N_NODES 131072
#define NPER    4096
#define NBATCH  32
#define D       32
#define NREL    10
#define NG      14   // num_g_rels
#define SPLIT   16   // path sub-blocks per batch
#define OUT2_OFF (NBATCH * (NG + 1) * D)         // 15360
#define OUT3_OFF (OUT2_OFF + NBATCH * D)         // 16384

// ---------------- scratch (device globals; no allocation allowed) ----------------
__device__ __align__(16) float g_w1[N_NODES * D];
__device__ __align__(16) float g_U [N_NODES * D];
__device__ __align__(16) float g_V [N_NODES * D];
__device__ __align__(16) float g_S [N_NODES * 16];   // per-(node, rel) norm sums (16 pad)
__device__ __align__(16) float g_nf[N_NODES * D];
__device__ unsigned char g_act[N_NODES];         // dst-activity map (rebuilt each run)
__device__ int   g_list[N_NODES];                // compacted active-node indices
__device__ int   g_cnt;                          // invariant: 0 at entry
__device__ int   g_ctr_path;                     // invariant: 0 at entry
__device__ float g_M1[D * D];     // (W2a - W2b) @ W_line
__device__ float g_M2[D * D];     // W2c @ W_line
__device__ float g_M3[D * D];     // self_loop_w @ W_line
__device__ float g_Cw[NREL * D];  // (attn_r @ (W2a+W2b) + b2) @ W_line
__device__ float g_pm[NBATCH * SPLIT];
__device__ float g_ps[NBATCH * SPLIT];
__device__ __align__(16) float g_pv[NBATCH * SPLIT * D];

__device__ __forceinline__ void red_add_v4(float* p, float4 v) {
    asm volatile("red.global.add.v4.f32 [%0], {%1,%2,%3,%4};"
                 :: "l"(p), "f"(v.x), "f"(v.y), "f"(v.z), "f"(v.w) : "memory");
}
__device__ __forceinline__ float fsel(const float4& q, int c) {
    return c == 0 ? q.x : (c == 1 ? q.y : (c == 2 ? q.z : q.w));
}

// ---------------- init: prep (block 0) + zero out + activity/compaction (+active-row zero) + w1 ----------------
__global__ void k_init(const float* __restrict__ feat, const float* __restrict__ Ww,
                       const float* __restrict__ bw,
                       const float* __restrict__ W2, const float* __restrict__ b2,
                       const float* __restrict__ attn, const float* __restrict__ SL,
                       const float* __restrict__ Wl,
                       float* __restrict__ out,
                       const int* __restrict__ idx1, const int* __restrict__ idx2,
                       const int* __restrict__ tar, int n_nodes) {
    if (blockIdx.x == 0) {
        __shared__ float Cs[NREL * D];
        int t = threadIdx.x;
        for (int i = t; i < NREL * D; i += blockDim.x) {
            int r = i / D, j = i % D;
            float acc = b2[j];
            #pragma unroll
            for (int k = 0; k < D; k++)
                acc += attn[r * D + k] * (W2[k * D + j] + W2[(D + k) * D + j]);
            Cs[i] = acc;
        }
        __syncthreads();
        for (int i = t; i < D * D; i += blockDim.x) {
            int k = i / D, d = i % D;
            float m1 = 0.f, m2 = 0.f, m3 = 0.f;
            #pragma unroll
            for (int j = 0; j < D; j++) {
                float wl = Wl[j * D + d];
                m1 += (W2[k * D + j] - W2[(D + k) * D + j]) * wl;
                m2 += W2[(2 * D + k) * D + j] * wl;
                m3 += SL[k * D + j] * wl;
            }
            g_M1[i] = m1; g_M2[i] = m2; g_M3[i] = m3;
        }
        for (int i = t; i < NREL * D; i += blockDim.x) {
            int r = i / D, d = i % D;
            float acc = 0.f;
            #pragma unroll
            for (int j = 0; j < D; j++) acc += Cs[r * D + j] * Wl[j * D + d];
            g_Cw[i] = acc;
        }
    }

    int tid = blockIdx.x * blockDim.x + threadIdx.x;
    int stride = gridDim.x * blockDim.x;
    if (tid < OUT3_OFF) out[tid] = 0.f;

    // activity map + compaction + zero U/V/S rows of ACTIVE nodes only (g_cnt == 0 at entry)
    {
        int n = tid;                              // stride >= n_nodes
        bool active = false;
        if (n < n_nodes) {
            active = (__ldg(&idx1[n]) == 1) || (__ldg(&idx2[n]) != 0) || (__ldg(&tar[n]) == 1);
            g_act[n] = active ? 1 : 0;
            if (active) {
                float4 z = make_float4(0.f, 0.f, 0.f, 0.f);
                float4* U4 = reinterpret_cast<float4*>(g_U) + n * 8;
                float4* V4 = reinterpret_cast<float4*>(g_V) + n * 8;
                float4* S4 = reinterpret_cast<float4*>(g_S) + n * 4;
                #pragma unroll
                for (int j = 0; j < 8; j++) { U4[j] = z; V4[j] = z; }
                #pragma unroll
                for (int j = 0; j < 4; j++) S4[j] = z;
            }
        }
        unsigned m = __ballot_sync(0xffffffffu, active);
        if (m) {
            int lane = threadIdx.x & 31;
            int rank = __popc(m & ((1u << lane) - 1u));
            int base = 0;
            if (lane == __ffs(m) - 1) base = atomicAdd(&g_cnt, __popc(m));
            base = __shfl_sync(0xffffffffu, base, __ffs(m) - 1);
            if (active) g_list[base + rank] = n;
        }
    }

    // w1 = feat @ W_w + b_w : 16 nodes/warp
    __shared__ __align__(16) float Ws[D * D];
    for (int i = threadIdx.x; i < D * D; i += blockDim.x) Ws[i] = Ww[i];
    __syncthreads();
    const float4* Ws4 = reinterpret_cast<const float4*>(Ws);
    int lane = threadIdx.x & 31;
    int sub  = lane & 7;
    int grp  = lane >> 3;
    int warp = tid >> 5;
    int nw   = stride >> 5;
    float4 b4 = __ldg(reinterpret_cast<const float4*>(bw) + sub);
    for (int base = warp * 16; base < n_nodes; base += nw * 16) {
        float4 f4[4], acc[4];
        #pragma unroll
        for (int t = 0; t < 4; t++) {
            int n = base + grp * 4 + t;           // n_nodes % 16 == 0
            f4[t]  = *reinterpret_cast<const float4*>(&feat[n * D + sub * 4]);
            acc[t] = b4;
        }
        #pragma unroll
        for (int k = 0; k < D; k++) {
            float4 w = Ws4[k * 8 + sub];
            #pragma unroll
            for (int t = 0; t < 4; t++) {
                float fk = __shfl_sync(0xffffffffu, fsel(f4[t], k & 3), k >> 2, 8);
                acc[t].x += fk * w.x; acc[t].y += fk * w.y;
                acc[t].z += fk * w.z; acc[t].w += fk * w.w;
            }
        }
        #pragma unroll
        for (int t = 0; t < 4; t++) {
            int n = base + grp * 4 + t;
            *reinterpret_cast<float4*>(&g_w1[n * D + sub * 4]) = acc[t];
        }
    }
}

// ---------------- edge stage: 16 edges/warp-iter, split load/process, ACTIVE-dst filter ----------------
__global__ void k_edge(const int* __restrict__ src, const int* __restrict__ dst,
                       const int* __restrict__ ety, const float* __restrict__ norm,
                       const float* __restrict__ attn, int nE) {
    __shared__ float4 et_s[NREL * 8];
    for (int i = threadIdx.x; i < NREL * 8; i += blockDim.x)
        et_s[i] = reinterpret_cast<const float4*>(attn)[i];
    __syncthreads();
    int lane = threadIdx.x & 31;
    int sub  = lane & 7;
    int grp  = lane >> 3;
    int warp = (blockIdx.x * blockDim.x + threadIdx.x) >> 5;
    int nw   = (gridDim.x * blockDim.x) >> 5;
    for (int e0 = warp * 16; e0 < nE; e0 += nw * 16) {
        // phase 1: batched metadata loads (MLP)
        bool aa[4];
        int  ss[4], rr[4];
        float nm[4];
        #pragma unroll
        for (int u = 0; u < 4; u++) {
            int e = e0 + u * 4 + grp;
            aa[u] = false;
            if (e < nE) {
                int d = __ldg(&dst[e]);
                aa[u] = (g_act[d] != 0);
            }
            if (aa[u]) {
                ss[u] = __ldg(&src[e]);
                rr[u] = __ldg(&ety[e]);
                nm[u] = __ldg(&norm[e]);
            }
        }
        // phase 2: gather + RED
        #pragma unroll
        for (int u = 0; u < 4; u++) {
            if (!aa[u]) continue;
            int e = e0 + u * 4 + grp;
            int d = __ldg(&dst[e]);
            float4 f = *reinterpret_cast<const float4*>(&g_w1[ss[u] * D + sub * 4]);
            float4 t1 = make_float4(nm[u] * f.x, nm[u] * f.y, nm[u] * f.z, nm[u] * f.w);
            red_add_v4(&g_U[d * D + sub * 4], t1);
            float4 et = et_s[rr[u] * 8 + sub];
            float4 v  = make_float4(t1.x * et.x, t1.y * et.y, t1.z * et.z, t1.w * et.w);
            red_add_v4(&g_V[d * D + sub * 4], v);
            if (sub == 0) atomicAdd(&g_S[d * 16 + rr[u]], nm[u]);
        }
    }
}

// ---------------- combine + scatter over compacted list: 16 nodes/warp ----------------
__global__ void __launch_bounds__(256, 2)
k_nf(const float* __restrict__ feat, const float* __restrict__ bline,
     const int* __restrict__ idx1, const int* __restrict__ idx2,
     const int* __restrict__ f2, const int* __restrict__ tar,
     float* __restrict__ out) {
    __shared__ __align__(16) float M1s[D * D], M2s[D * D], M3s[D * D], Cws[NREL * D];
    for (int i = threadIdx.x; i < D * D; i += blockDim.x) {
        M1s[i] = g_M1[i]; M2s[i] = g_M2[i]; M3s[i] = g_M3[i];
    }
    for (int i = threadIdx.x; i < NREL * D; i += blockDim.x) Cws[i] = g_Cw[i];
    __syncthreads();
    const float4* M14 = reinterpret_cast<const float4*>(M1s);
    const float4* M24 = reinterpret_cast<const float4*>(M2s);
    const float4* M34 = reinterpret_cast<const float4*>(M3s);
    const float4* Cw4 = reinterpret_cast<const float4*>(Cws);
    int cnt  = g_cnt;
    int lane = threadIdx.x & 31;
    int sub  = lane & 7;
    int grp  = lane >> 3;
    int warp = (blockIdx.x * blockDim.x + threadIdx.x) >> 5;
    int nw   = (gridDim.x * blockDim.x) >> 5;
    float4 b4 = __ldg(reinterpret_cast<const float4*>(bline) + sub);

    for (int base = warp * 16; base < cnt; base += nw * 16) {
        int  n_t[4];
        bool val_t[4];
        float4 acc[4];
        #pragma unroll
        for (int t = 0; t < 4; t++) {
            int i = base + grp * 4 + t;
            val_t[t] = i < cnt;
            n_t[t] = g_list[val_t[t] ? i : 0];
            acc[t] = b4;
        }
        {
            float sv0[4], sv1[4];
            #pragma unroll
            for (int t = 0; t < 4; t++) {
                sv0[t] = g_S[n_t[t] * 16 + sub];
                sv1[t] = g_S[n_t[t] * 16 + 8 + sub];
            }
            #pragma unroll
            for (int r = 0; r < NREL; r++) {
                float4 c = Cw4[r * 8 + sub];
                #pragma unroll
                for (int t = 0; t < 4; t++) {
                    float s_r = __shfl_sync(0xffffffffu, r < 8 ? sv0[t] : sv1[t], r & 7, 8);
                    acc[t].x += s_r * c.x; acc[t].y += s_r * c.y;
                    acc[t].z += s_r * c.z; acc[t].w += s_r * c.w;
                }
            }
        }
        {
            float4 u4[4], v4[4], f4[4];
            #pragma unroll
            for (int t = 0; t < 4; t++) {
                u4[t] = *reinterpret_cast<const float4*>(&g_U[n_t[t] * D + sub * 4]);
                v4[t] = *reinterpret_cast<const float4*>(&g_V[n_t[t] * D + sub * 4]);
                f4[t] = *reinterpret_cast<const float4*>(&feat[n_t[t] * D + sub * 4]);
            }
            #pragma unroll
            for (int k = 0; k < D; k++) {
                float4 m1 = M14[k * 8 + sub];
                float4 m2 = M24[k * 8 + sub];
                float4 m3 = M34[k * 8 + sub];
                #pragma unroll
                for (int t = 0; t < 4; t++) {
                    float uk = __shfl_sync(0xffffffffu, fsel(u4[t], k & 3), k >> 2, 8);
                    float vk = __shfl_sync(0xffffffffu, fsel(v4[t], k & 3), k >> 2, 8);
                    float fk = __shfl_sync(0xffffffffu, fsel(f4[t], k & 3), k >> 2, 8);
                    acc[t].x += uk * m1.x + vk * m2.x + fk * m3.x;
                    acc[t].y += uk * m1.y + vk * m2.y + fk * m3.y;
                    acc[t].z += uk * m1.z + vk * m2.z + fk * m3.z;
                    acc[t].w += uk * m1.w + vk * m2.w + fk * m3.w;
                }
            }
        }
        #pragma unroll
        for (int t = 0; t < 4; t++) {
            if (!val_t[t]) continue;
            int n = n_t[t];
            float4 val = make_float4(fmaxf(acc[t].x, 0.f), fmaxf(acc[t].y, 0.f),
                                     fmaxf(acc[t].z, 0.f), fmaxf(acc[t].w, 0.f));
            int b  = n >> 12;                     // n / NPER
            int i1 = __ldg(&idx1[n]);
            int i2 = __ldg(&idx2[n]);
            int tr = __ldg(&tar[n]);
            if (i1 == 1)
                *reinterpret_cast<float4*>(&g_nf[n * D + sub * 4]) = val;
            if (i2 != 0) {
                int slot = __ldg(&f2[n]) + 1;     // index_offset = 1
                if (slot <= NG)                   // slot NG+1 = dump row (dropped)
                    *reinterpret_cast<float4*>(&out[(b * (NG + 1) + slot) * D + sub * 4]) = val;
            }
            if (tr == 1)
                red_add_v4(&out[OUT2_OFF + b * D + sub * 4], val);
        }
    }
}

// ---------------- path softmax: partials (rows cached in SMEM) + last-block combine ----------------
#define RSTRIDE 36   // floats per cached row (16B-aligned, conflict-degree-4)
__global__ void k_path(const int* __restrict__ idx1, const float* __restrict__ zero_path,
                       float* __restrict__ out) {
    const int R = NPER / SPLIT;                   // 256 rows per block
    __shared__ float sc[R];
    __shared__ __align__(16) float rows[R * RSTRIDE];  // 36KB row cache
    __shared__ float tgt[D];
    __shared__ float red[8];
    __shared__ float wacc[8][D];
    __shared__ int isLast;
    int b = blockIdx.x / SPLIT, j = blockIdx.x % SPLIT;
    int t = threadIdx.x;
    int w = t >> 5, lane = t & 31;
    if (t < D) tgt[t] = out[OUT2_OFF + b * D + t];
    __syncthreads();
    size_t rbase = (size_t)b * NPER + (size_t)j * R;

    // scores + row caching (each thread owns row i = t)
    for (int i = t; i < R; i += 256) {
        float s = -1e30f;
        if (idx1[rbase + i] == 1) {
            const float4* row = reinterpret_cast<const float4*>(g_nf + (rbase + i) * D);
            float4* dstp = reinterpret_cast<float4*>(&rows[i * RSTRIDE]);
            float acc = 0.f;
            #pragma unroll
            for (int k = 0; k < 8; k++) {
                float4 r4 = row[k];
                dstp[k] = r4;
                acc += r4.x * tgt[k * 4 + 0] + r4.y * tgt[k * 4 + 1]
                     + r4.z * tgt[k * 4 + 2] + r4.w * tgt[k * 4 + 3];
            }
            s = acc;
        }
        sc[i] = s;
    }
    __syncthreads();

    float m = -1e30f;
    for (int i = t; i < R; i += 256) m = fmaxf(m, sc[i]);
    #pragma unroll
    for (int off = 16; off > 0; off >>= 1)
        m = fmaxf(m, __shfl_xor_sync(0xffffffffu, m, off));
    if (lane == 0) red[w] = m;
    __syncthreads();
    if (t < 8) {
        float mm = red[t];
        #pragma unroll
        for (int off = 4; off > 0; off >>= 1)
            mm = fmaxf(mm, __shfl_xor_sync(0xffu, mm, off));
        red[t] = mm;
    }
    __syncthreads();
    float mloc = red[0];
    __syncthreads();

    if (mloc < -1e29f) {                          // empty sub-block
        if (t == 0) { g_pm[blockIdx.x] = -1e30f; g_ps[blockIdx.x] = 0.f; }
        if (t < D) g_pv[blockIdx.x * D + t] = 0.f;
    } else {
        float ssum = 0.f;
        for (int i = t; i < R; i += 256) {
            float e = (sc[i] > -1e29f) ? __expf(sc[i] - mloc) : 0.f;
            sc[i] = e;
            ssum += e;
        }
        #pragma unroll
        for (int off = 16; off > 0; off >>= 1)
            ssum += __shfl_xor_sync(0xffffffffu, ssum, off);
        if (lane == 0) red[w] = ssum;
        __syncthreads();
        if (t < 8) {
            float s2 = red[t];
            #pragma unroll
            for (int off = 4; off > 0; off >>= 1)
                s2 += __shfl_xor_sync(0xffu, s2, off);
            red[t] = s2;
        }
        __syncthreads();
        float sloc = red[0];

        // weighted aggregation from the SMEM row cache
        float a = 0.f;
        for (int i = w; i < R; i += 8) {
            float e = sc[i];
            if (e == 0.f) continue;
            a += e * rows[i * RSTRIDE + lane];
        }
        wacc[w][lane] = a;
        __syncthreads();
        if (t < D) {
            float acc = 0.f;
            #pragma unroll
            for (int q = 0; q < 8; q++) acc += wacc[q][t];
            g_pv[blockIdx.x * D + t] = acc;
        }
        if (t == 0) { g_pm[blockIdx.x] = mloc; g_ps[blockIdx.x] = sloc; }
    }

    __threadfence();
    if (t == 0) isLast = (atomicAdd(&g_ctr_path, 1) == NBATCH * SPLIT - 1);
    __syncthreads();
    if (!isLast) return;
    __threadfence();
    if (t == 0) { g_ctr_path = 0; g_cnt = 0; }    // restore invariants

    for (int o = t; o < NBATCH * D; o += 256) {
        int bb = o >> 5, d = o & 31;
        float M = -1e30f;
        #pragma unroll
        for (int q = 0; q < SPLIT; q++) M = fmaxf(M, g_pm[bb * SPLIT + q]);
        if (M < -1e29f) {
            out[OUT3_OFF + o] = zero_path[d];
        } else {
            float S = 0.f, v = 0.f;
            #pragma unroll
            for (int q = 0; q < SPLIT; q++) {
                float scale = __expf(g_pm[bb * SPLIT + q] - M);
                S += scale * g_ps[bb * SPLIT + q];
                v += scale * g_pv[(bb * SPLIT + q) * D + d];
            }
            out[OUT3_OFF + o] = v / S;
        }
    }
}

// ---------------- launch ----------------
extern "C" void kernel_launch(void* const* d_in, const int* in_sizes, int n_in,
                              void* d_out, int out_size) {
    const float* feat = (const float*)d_in[0];
    const float* norm = (const float*)d_in[1];
    const float* W_w  = (const float*)d_in[2];
    const float* b_w  = (const float*)d_in[3];
    const float* W2   = (const float*)d_in[4];
    const float* b2   = (const float*)d_in[5];
    const float* attn = (const float*)d_in[6];
    const float* SL   = (const float*)d_in[7];
    const float* Wl   = (const float*)d_in[8];
    const float* bl   = (const float*)d_in[9];
    const float* zp   = (const float*)d_in[10];
    const int*   src  = (const int*)d_in[11];
    const int*   dst  = (const int*)d_in[12];
    const int*   ety  = (const int*)d_in[13];
    const int*   idx1 = (const int*)d_in[14];
    const int*   idx2 = (const int*)d_in[15];
    const int*   f2   = (const int*)d_in[16];
    const int*   tar  = (const int*)d_in[17];

    int nE     = in_sizes[11];
    int nNodes = in_sizes[0] / D;
    float* out = (float*)d_out;

    k_init<<<1184, 256>>>(feat, W_w, b_w, W2, b2, attn, SL, Wl, out,
                          idx1, idx2, tar, nNodes);
    k_edge<<<1184, 256>>>(src, dst, ety, norm, attn, nE);
    k_nf  <<<520, 256>>>(feat, bl, idx1, idx2, f2, tar, out);
    k_path<<<NBATCH * SPLIT, 256>>>(idx1, zp, out);
}

// round 11
// speedup vs baseline: 1.0586x; 1.0586x over previous
#include <cuda_runtime.h>

#define N_NODES 131072
#define NPER    4096
#define NBATCH  32
#define D       32
#define NREL    10
#define NG      14   // num_g_rels
#define SPLIT   16   // path sub-blocks per batch
#define OUT2_OFF (NBATCH * (NG + 1) * D)         // 15360
#define OUT3_OFF (OUT2_OFF + NBATCH * D)         // 16384

// ---------------- scratch (device globals; no allocation allowed) ----------------
__device__ __align__(16) float g_w1[N_NODES * D];
__device__ __align__(16) float g_U [N_NODES * D];
__device__ __align__(16) float g_V [N_NODES * D];
__device__ __align__(16) float g_S [N_NODES * 16];   // per-(node, rel) norm sums (16 pad)
__device__ __align__(16) float g_nf[N_NODES * D];
__device__ unsigned char g_act[N_NODES];         // dst-activity map (rebuilt each run)
__device__ int   g_list[N_NODES];                // compacted active-node indices
__device__ int   g_cnt;                          // invariant: 0 at entry
__device__ int   g_ctr_path;                     // invariant: 0 at entry
__device__ float g_M1[D * D];     // (W2a - W2b) @ W_line
__device__ float g_M2[D * D];     // W2c @ W_line
__device__ float g_M3[D * D];     // self_loop_w @ W_line
__device__ float g_Cw[NREL * D];  // (attn_r @ (W2a+W2b) + b2) @ W_line
__device__ float g_pm[NBATCH * SPLIT];
__device__ float g_ps[NBATCH * SPLIT];
__device__ __align__(16) float g_pv[NBATCH * SPLIT * D];

__device__ __forceinline__ void red_add_v4(float* p, float4 v) {
    asm volatile("red.global.add.v4.f32 [%0], {%1,%2,%3,%4};"
                 :: "l"(p), "f"(v.x), "f"(v.y), "f"(v.z), "f"(v.w) : "memory");
}
__device__ __forceinline__ float fsel(const float4& q, int c) {
    return c == 0 ? q.x : (c == 1 ? q.y : (c == 2 ? q.z : q.w));
}

// ---------------- init: prep (block 0) + zero out/U/V/S + activity/compaction + w1 ----------------
__global__ void k_init(const float* __restrict__ feat, const float* __restrict__ Ww,
                       const float* __restrict__ bw,
                       const float* __restrict__ W2, const float* __restrict__ b2,
                       const float* __restrict__ attn, const float* __restrict__ SL,
                       const float* __restrict__ Wl,
                       float* __restrict__ out,
                       const int* __restrict__ idx1, const int* __restrict__ idx2,
                       const int* __restrict__ tar, int n_nodes) {
    if (blockIdx.x == 0) {
        __shared__ float Cs[NREL * D];
        int t = threadIdx.x;
        for (int i = t; i < NREL * D; i += blockDim.x) {
            int r = i / D, j = i % D;
            float acc = b2[j];
            #pragma unroll
            for (int k = 0; k < D; k++)
                acc += attn[r * D + k] * (W2[k * D + j] + W2[(D + k) * D + j]);
            Cs[i] = acc;
        }
        __syncthreads();
        for (int i = t; i < D * D; i += blockDim.x) {
            int k = i / D, d = i % D;
            float m1 = 0.f, m2 = 0.f, m3 = 0.f;
            #pragma unroll
            for (int j = 0; j < D; j++) {
                float wl = Wl[j * D + d];
                m1 += (W2[k * D + j] - W2[(D + k) * D + j]) * wl;
                m2 += W2[(2 * D + k) * D + j] * wl;
                m3 += SL[k * D + j] * wl;
            }
            g_M1[i] = m1; g_M2[i] = m2; g_M3[i] = m3;
        }
        for (int i = t; i < NREL * D; i += blockDim.x) {
            int r = i / D, d = i % D;
            float acc = 0.f;
            #pragma unroll
            for (int j = 0; j < D; j++) acc += Cs[r * D + j] * Wl[j * D + d];
            g_Cw[i] = acc;
        }
    }

    int tid = blockIdx.x * blockDim.x + threadIdx.x;
    int stride = gridDim.x * blockDim.x;
    if (tid < OUT3_OFF) out[tid] = 0.f;

    // zero U/V/S accumulators (contiguous, coalesced)
    float4 z = make_float4(0.f, 0.f, 0.f, 0.f);
    const int nUV = N_NODES * D / 4;
    for (int j = tid; j < nUV; j += stride) {
        reinterpret_cast<float4*>(g_U)[j] = z;
        reinterpret_cast<float4*>(g_V)[j] = z;
    }
    const int nS = N_NODES * 16 / 4;
    for (int j = tid; j < nS; j += stride)
        reinterpret_cast<float4*>(g_S)[j] = z;

    // activity map + compaction (g_cnt == 0 at entry)
    {
        int n = tid;                              // stride >= n_nodes
        bool active = false;
        if (n < n_nodes) {
            active = (__ldg(&idx1[n]) == 1) || (__ldg(&idx2[n]) != 0) || (__ldg(&tar[n]) == 1);
            g_act[n] = active ? 1 : 0;
        }
        unsigned m = __ballot_sync(0xffffffffu, active);
        if (m) {
            int lane = threadIdx.x & 31;
            int rank = __popc(m & ((1u << lane) - 1u));
            int base = 0;
            if (lane == __ffs(m) - 1) base = atomicAdd(&g_cnt, __popc(m));
            base = __shfl_sync(0xffffffffu, base, __ffs(m) - 1);
            if (active) g_list[base + rank] = n;
        }
    }

    // w1 = feat @ W_w + b_w : 16 nodes/warp
    __shared__ __align__(16) float Ws[D * D];
    for (int i = threadIdx.x; i < D * D; i += blockDim.x) Ws[i] = Ww[i];
    __syncthreads();
    const float4* Ws4 = reinterpret_cast<const float4*>(Ws);
    int lane = threadIdx.x & 31;
    int sub  = lane & 7;
    int grp  = lane >> 3;
    int warp = tid >> 5;
    int nw   = stride >> 5;
    float4 b4 = __ldg(reinterpret_cast<const float4*>(bw) + sub);
    for (int base = warp * 16; base < n_nodes; base += nw * 16) {
        float4 f4[4], acc[4];
        #pragma unroll
        for (int t = 0; t < 4; t++) {
            int n = base + grp * 4 + t;           // n_nodes % 16 == 0
            f4[t]  = *reinterpret_cast<const float4*>(&feat[n * D + sub * 4]);
            acc[t] = b4;
        }
        #pragma unroll
        for (int k = 0; k < D; k++) {
            float4 w = Ws4[k * 8 + sub];
            #pragma unroll
            for (int t = 0; t < 4; t++) {
                float fk = __shfl_sync(0xffffffffu, fsel(f4[t], k & 3), k >> 2, 8);
                acc[t].x += fk * w.x; acc[t].y += fk * w.y;
                acc[t].z += fk * w.z; acc[t].w += fk * w.w;
            }
        }
        #pragma unroll
        for (int t = 0; t < 4; t++) {
            int n = base + grp * 4 + t;
            *reinterpret_cast<float4*>(&g_w1[n * D + sub * 4]) = acc[t];
        }
    }
}

// ---------------- edge stage: 4 edges/warp, ACTIVE-dst filter, float4, vector RED, unroll 2 ----------------
__global__ void k_edge(const int* __restrict__ src, const int* __restrict__ dst,
                       const int* __restrict__ ety, const float* __restrict__ norm,
                       const float* __restrict__ attn, int nE) {
    __shared__ float4 et_s[NREL * 8];
    for (int i = threadIdx.x; i < NREL * 8; i += blockDim.x)
        et_s[i] = reinterpret_cast<const float4*>(attn)[i];
    __syncthreads();
    int lane = threadIdx.x & 31;
    int sub  = lane & 7;
    int grp  = lane >> 3;
    int warp = (blockIdx.x * blockDim.x + threadIdx.x) >> 5;
    int nw   = (gridDim.x * blockDim.x) >> 5;
    for (int e0 = warp * 8; e0 < nE; e0 += nw * 8) {
        #pragma unroll
        for (int u = 0; u < 2; u++) {
            int e = e0 + u * 4 + grp;
            if (e >= nE) continue;
            int d = __ldg(&dst[e]);
            if (!g_act[d]) continue;              // inactive dst: dead work
            int   s  = __ldg(&src[e]);
            int   r  = __ldg(&ety[e]);
            float nm = __ldg(&norm[e]);
            float4 f = *reinterpret_cast<const float4*>(&g_w1[s * D + sub * 4]);
            float4 t1 = make_float4(nm * f.x, nm * f.y, nm * f.z, nm * f.w);
            red_add_v4(&g_U[d * D + sub * 4], t1);
            float4 et = et_s[r * 8 + sub];
            float4 v  = make_float4(t1.x * et.x, t1.y * et.y, t1.z * et.z, t1.w * et.w);
            red_add_v4(&g_V[d * D + sub * 4], v);
            if (sub == 0) atomicAdd(&g_S[d * 16 + r], nm);
        }
    }
}

// ---------------- combine + scatter over compacted list: 16 nodes/warp ----------------
__global__ void __launch_bounds__(256, 2)
k_nf(const float* __restrict__ feat, const float* __restrict__ bline,
     const int* __restrict__ idx1, const int* __restrict__ idx2,
     const int* __restrict__ f2, const int* __restrict__ tar,
     float* __restrict__ out) {
    __shared__ __align__(16) float M1s[D * D], M2s[D * D], M3s[D * D], Cws[NREL * D];
    for (int i = threadIdx.x; i < D * D; i += blockDim.x) {
        M1s[i] = g_M1[i]; M2s[i] = g_M2[i]; M3s[i] = g_M3[i];
    }
    for (int i = threadIdx.x; i < NREL * D; i += blockDim.x) Cws[i] = g_Cw[i];
    __syncthreads();
    const float4* M14 = reinterpret_cast<const float4*>(M1s);
    const float4* M24 = reinterpret_cast<const float4*>(M2s);
    const float4* M34 = reinterpret_cast<const float4*>(M3s);
    const float4* Cw4 = reinterpret_cast<const float4*>(Cws);
    int cnt  = g_cnt;
    int lane = threadIdx.x & 31;
    int sub  = lane & 7;
    int grp  = lane >> 3;
    int warp = (blockIdx.x * blockDim.x + threadIdx.x) >> 5;
    int nw   = (gridDim.x * blockDim.x) >> 5;
    float4 b4 = __ldg(reinterpret_cast<const float4*>(bline) + sub);

    for (int base = warp * 16; base < cnt; base += nw * 16) {
        int  n_t[4];
        bool val_t[4];
        float4 acc[4];
        #pragma unroll
        for (int t = 0; t < 4; t++) {
            int i = base + grp * 4 + t;
            val_t[t] = i < cnt;
            n_t[t] = g_list[val_t[t] ? i : 0];
            acc[t] = b4;
        }
        {
            float sv0[4], sv1[4];
            #pragma unroll
            for (int t = 0; t < 4; t++) {
                sv0[t] = g_S[n_t[t] * 16 + sub];
                sv1[t] = g_S[n_t[t] * 16 + 8 + sub];
            }
            #pragma unroll
            for (int r = 0; r < NREL; r++) {
                float4 c = Cw4[r * 8 + sub];
                #pragma unroll
                for (int t = 0; t < 4; t++) {
                    float s_r = __shfl_sync(0xffffffffu, r < 8 ? sv0[t] : sv1[t], r & 7, 8);
                    acc[t].x += s_r * c.x; acc[t].y += s_r * c.y;
                    acc[t].z += s_r * c.z; acc[t].w += s_r * c.w;
                }
            }
        }
        {
            float4 u4[4], v4[4], f4[4];
            #pragma unroll
            for (int t = 0; t < 4; t++) {
                u4[t] = *reinterpret_cast<const float4*>(&g_U[n_t[t] * D + sub * 4]);
                v4[t] = *reinterpret_cast<const float4*>(&g_V[n_t[t] * D + sub * 4]);
                f4[t] = *reinterpret_cast<const float4*>(&feat[n_t[t] * D + sub * 4]);
            }
            #pragma unroll
            for (int k = 0; k < D; k++) {
                float4 m1 = M14[k * 8 + sub];
                float4 m2 = M24[k * 8 + sub];
                float4 m3 = M34[k * 8 + sub];
                #pragma unroll
                for (int t = 0; t < 4; t++) {
                    float uk = __shfl_sync(0xffffffffu, fsel(u4[t], k & 3), k >> 2, 8);
                    float vk = __shfl_sync(0xffffffffu, fsel(v4[t], k & 3), k >> 2, 8);
                    float fk = __shfl_sync(0xffffffffu, fsel(f4[t], k & 3), k >> 2, 8);
                    acc[t].x += uk * m1.x + vk * m2.x + fk * m3.x;
                    acc[t].y += uk * m1.y + vk * m2.y + fk * m3.y;
                    acc[t].z += uk * m1.z + vk * m2.z + fk * m3.z;
                    acc[t].w += uk * m1.w + vk * m2.w + fk * m3.w;
                }
            }
        }
        #pragma unroll
        for (int t = 0; t < 4; t++) {
            if (!val_t[t]) continue;
            int n = n_t[t];
            float4 val = make_float4(fmaxf(acc[t].x, 0.f), fmaxf(acc[t].y, 0.f),
                                     fmaxf(acc[t].z, 0.f), fmaxf(acc[t].w, 0.f));
            int b  = n >> 12;                     // n / NPER
            int i1 = __ldg(&idx1[n]);
            int i2 = __ldg(&idx2[n]);
            int tr = __ldg(&tar[n]);
            if (i1 == 1)
                *reinterpret_cast<float4*>(&g_nf[n * D + sub * 4]) = val;
            if (i2 != 0) {
                int slot = __ldg(&f2[n]) + 1;     // index_offset = 1
                if (slot <= NG)                   // slot NG+1 = dump row (dropped)
                    *reinterpret_cast<float4*>(&out[(b * (NG + 1) + slot) * D + sub * 4]) = val;
            }
            if (tr == 1)
                red_add_v4(&out[OUT2_OFF + b * D + sub * 4], val);
        }
    }
}

// ---------------- path softmax: unconditional row loads (break idx1->row latency chain) ----------------
#define RSTRIDE 36   // floats per cached row (16B-aligned)
__global__ void k_path(const int* __restrict__ idx1, const float* __restrict__ zero_path,
                       float* __restrict__ out) {
    const int R = NPER / SPLIT;                   // 256 rows per block
    __shared__ float sc[R];
    __shared__ __align__(16) float rows[R * RSTRIDE];  // 36KB row cache
    __shared__ float tgt[D];
    __shared__ float red[8];
    __shared__ float wacc[8][D];
    __shared__ int isLast;
    int b = blockIdx.x / SPLIT, j = blockIdx.x % SPLIT;
    int t = threadIdx.x;
    int w = t >> 5, lane = t & 31;
    if (t < D) tgt[t] = out[OUT2_OFF + b * D + t];
    __syncthreads();
    size_t rbase = (size_t)b * NPER + (size_t)j * R;

    // scores: issue idx1 AND row loads in parallel, select afterwards.
    // (rows of non-path nodes hold stale data; the select discards them.)
    for (int i = t; i < R; i += 256) {
        int a = __ldg(&idx1[rbase + i]);
        const float4* row = reinterpret_cast<const float4*>(g_nf + (rbase + i) * D);
        float4* dstp = reinterpret_cast<float4*>(&rows[i * RSTRIDE]);
        float acc = 0.f;
        #pragma unroll
        for (int k = 0; k < 8; k++) {
            float4 r4 = row[k];
            dstp[k] = r4;
            acc += r4.x * tgt[k * 4 + 0] + r4.y * tgt[k * 4 + 1]
                 + r4.z * tgt[k * 4 + 2] + r4.w * tgt[k * 4 + 3];
        }
        sc[i] = (a == 1) ? acc : -1e30f;
    }
    __syncthreads();

    float m = -1e30f;
    for (int i = t; i < R; i += 256) m = fmaxf(m, sc[i]);
    #pragma unroll
    for (int off = 16; off > 0; off >>= 1)
        m = fmaxf(m, __shfl_xor_sync(0xffffffffu, m, off));
    if (lane == 0) red[w] = m;
    __syncthreads();
    if (t < 8) {
        float mm = red[t];
        #pragma unroll
        for (int off = 4; off > 0; off >>= 1)
            mm = fmaxf(mm, __shfl_xor_sync(0xffu, mm, off));
        red[t] = mm;
    }
    __syncthreads();
    float mloc = red[0];
    __syncthreads();

    if (mloc < -1e29f) {                          // empty sub-block
        if (t == 0) { g_pm[blockIdx.x] = -1e30f; g_ps[blockIdx.x] = 0.f; }
        if (t < D) g_pv[blockIdx.x * D + t] = 0.f;
    } else {
        float ssum = 0.f;
        for (int i = t; i < R; i += 256) {
            float e = (sc[i] > -1e29f) ? __expf(sc[i] - mloc) : 0.f;
            sc[i] = e;
            ssum += e;
        }
        #pragma unroll
        for (int off = 16; off > 0; off >>= 1)
            ssum += __shfl_xor_sync(0xffffffffu, ssum, off);
        if (lane == 0) red[w] = ssum;
        __syncthreads();
        if (t < 8) {
            float s2 = red[t];
            #pragma unroll
            for (int off = 4; off > 0; off >>= 1)
                s2 += __shfl_xor_sync(0xffu, s2, off);
            red[t] = s2;
        }
        __syncthreads();
        float sloc = red[0];

        // weighted aggregation from the SMEM row cache (e==0 skip guards stale rows)
        float a = 0.f;
        for (int i = w; i < R; i += 8) {
            float e = sc[i];
            if (e == 0.f) continue;
            a += e * rows[i * RSTRIDE + lane];
        }
        wacc[w][lane] = a;
        __syncthreads();
        if (t < D) {
            float acc = 0.f;
            #pragma unroll
            for (int q = 0; q < 8; q++) acc += wacc[q][t];
            g_pv[blockIdx.x * D + t] = acc;
        }
        if (t == 0) { g_pm[blockIdx.x] = mloc; g_ps[blockIdx.x] = sloc; }
    }

    __threadfence();
    if (t == 0) isLast = (atomicAdd(&g_ctr_path, 1) == NBATCH * SPLIT - 1);
    __syncthreads();
    if (!isLast) return;
    __threadfence();
    if (t == 0) { g_ctr_path = 0; g_cnt = 0; }    // restore invariants

    for (int o = t; o < NBATCH * D; o += 256) {
        int bb = o >> 5, d = o & 31;
        float M = -1e30f;
        #pragma unroll
        for (int q = 0; q < SPLIT; q++) M = fmaxf(M, g_pm[bb * SPLIT + q]);
        if (M < -1e29f) {
            out[OUT3_OFF + o] = zero_path[d];
        } else {
            float S = 0.f, v = 0.f;
            #pragma unroll
            for (int q = 0; q < SPLIT; q++) {
                float scale = __expf(g_pm[bb * SPLIT + q] - M);
                S += scale * g_ps[bb * SPLIT + q];
                v += scale * g_pv[(bb * SPLIT + q) * D + d];
            }
            out[OUT3_OFF + o] = v / S;
        }
    }
}

// ---------------- launch ----------------
extern "C" void kernel_launch(void* const* d_in, const int* in_sizes, int n_in,
                              void* d_out, int out_size) {
    const float* feat = (const float*)d_in[0];
    const float* norm = (const float*)d_in[1];
    const float* W_w  = (const float*)d_in[2];
    const float* b_w  = (const float*)d_in[3];
    const float* W2   = (const float*)d_in[4];
    const float* b2   = (const float*)d_in[5];
    const float* attn = (const float*)d_in[6];
    const float* SL   = (const float*)d_in[7];
    const float* Wl   = (const float*)d_in[8];
    const float* bl   = (const float*)d_in[9];
    const float* zp   = (const float*)d_in[10];
    const int*   src  = (const int*)d_in[11];
    const int*   dst  = (const int*)d_in[12];
    const int*   ety  = (const int*)d_in[13];
    const int*   idx1 = (const int*)d_in[14];
    const int*   idx2 = (const int*)d_in[15];
    const int*   f2   = (const int*)d_in[16];
    const int*   tar  = (const int*)d_in[17];

    int nE     = in_sizes[11];
    int nNodes = in_sizes[0] / D;
    float* out = (float*)d_out;

    k_init<<<1184, 256>>>(feat, W_w, b_w, W2, b2, attn, SL, Wl, out,
                          idx1, idx2, tar, nNodes);
    k_edge<<<1184, 256>>>(src, dst, ety, norm, attn, nE);
    k_nf  <<<520, 256>>>(feat, bl, idx1, idx2, f2, tar, out);
    k_path<<<NBATCH * SPLIT, 256>>>(idx1, zp, out);
}

// round 12
// speedup vs baseline: 1.0960x; 1.0353x over previous
#include <cuda_runtime.h>

#define N_NODES 131072
#define NPER    4096
#define NBATCH  32
#define D       32
#define NREL    10
#define NG      14   // num_g_rels
#define SPLIT   8    // path sub-blocks per batch
#define OUT2_OFF (NBATCH * (NG + 1) * D)         // 15360
#define OUT3_OFF (OUT2_OFF + NBATCH * D)         // 16384

// ---------------- scratch (device globals; no allocation allowed) ----------------
__device__ __align__(16) float g_w1[N_NODES * D];
__device__ __align__(16) float g_U [N_NODES * D];
__device__ __align__(16) float g_V [N_NODES * D];
__device__ __align__(16) float g_S [N_NODES * 16];   // per-(node, rel) norm sums (16 pad)
__device__ __align__(16) float g_nf[N_NODES * D];
__device__ unsigned char g_act[N_NODES];         // dst-activity map (rebuilt each run)
__device__ int   g_list[N_NODES];                // compacted active-node indices
__device__ int   g_cnt;                          // invariant: 0 at entry
__device__ float g_M1[D * D];     // (W2a - W2b) @ W_line
__device__ float g_M2[D * D];     // W2c @ W_line
__device__ float g_M3[D * D];     // self_loop_w @ W_line
__device__ float g_Cw[NREL * D];  // (attn_r @ (W2a+W2b) + b2) @ W_line
__device__ float g_pm[NBATCH * SPLIT];
__device__ float g_ps[NBATCH * SPLIT];
__device__ __align__(16) float g_pv[NBATCH * SPLIT * D];

__device__ __forceinline__ void red_add_v4(float* p, float4 v) {
    asm volatile("red.global.add.v4.f32 [%0], {%1,%2,%3,%4};"
                 :: "l"(p), "f"(v.x), "f"(v.y), "f"(v.z), "f"(v.w) : "memory");
}
__device__ __forceinline__ float fsel(const float4& q, int c) {
    return c == 0 ? q.x : (c == 1 ? q.y : (c == 2 ? q.z : q.w));
}

// ---------------- init: prep (block 0) + zero out/U/V/S + activity/compaction + w1 ----------------
__global__ void k_init(const float* __restrict__ feat, const float* __restrict__ Ww,
                       const float* __restrict__ bw,
                       const float* __restrict__ W2, const float* __restrict__ b2,
                       const float* __restrict__ attn, const float* __restrict__ SL,
                       const float* __restrict__ Wl,
                       float* __restrict__ out,
                       const int* __restrict__ idx1, const int* __restrict__ idx2,
                       const int* __restrict__ tar, int n_nodes) {
    if (blockIdx.x == 0) {
        __shared__ float Cs[NREL * D];
        int t = threadIdx.x;
        for (int i = t; i < NREL * D; i += blockDim.x) {
            int r = i / D, j = i % D;
            float acc = b2[j];
            #pragma unroll
            for (int k = 0; k < D; k++)
                acc += attn[r * D + k] * (W2[k * D + j] + W2[(D + k) * D + j]);
            Cs[i] = acc;
        }
        __syncthreads();
        for (int i = t; i < D * D; i += blockDim.x) {
            int k = i / D, d = i % D;
            float m1 = 0.f, m2 = 0.f, m3 = 0.f;
            #pragma unroll
            for (int j = 0; j < D; j++) {
                float wl = Wl[j * D + d];
                m1 += (W2[k * D + j] - W2[(D + k) * D + j]) * wl;
                m2 += W2[(2 * D + k) * D + j] * wl;
                m3 += SL[k * D + j] * wl;
            }
            g_M1[i] = m1; g_M2[i] = m2; g_M3[i] = m3;
        }
        for (int i = t; i < NREL * D; i += blockDim.x) {
            int r = i / D, d = i % D;
            float acc = 0.f;
            #pragma unroll
            for (int j = 0; j < D; j++) acc += Cs[r * D + j] * Wl[j * D + d];
            g_Cw[i] = acc;
        }
    }

    int tid = blockIdx.x * blockDim.x + threadIdx.x;
    int stride = gridDim.x * blockDim.x;
    if (tid < OUT3_OFF) out[tid] = 0.f;

    // zero U/V/S accumulators (contiguous, coalesced)
    float4 z = make_float4(0.f, 0.f, 0.f, 0.f);
    const int nUV = N_NODES * D / 4;
    for (int j = tid; j < nUV; j += stride) {
        reinterpret_cast<float4*>(g_U)[j] = z;
        reinterpret_cast<float4*>(g_V)[j] = z;
    }
    const int nS = N_NODES * 16 / 4;
    for (int j = tid; j < nS; j += stride)
        reinterpret_cast<float4*>(g_S)[j] = z;

    // activity map + compaction (g_cnt == 0 at entry)
    {
        int n = tid;                              // stride >= n_nodes
        bool active = false;
        if (n < n_nodes) {
            active = (__ldg(&idx1[n]) == 1) || (__ldg(&idx2[n]) != 0) || (__ldg(&tar[n]) == 1);
            g_act[n] = active ? 1 : 0;
        }
        unsigned m = __ballot_sync(0xffffffffu, active);
        if (m) {
            int lane = threadIdx.x & 31;
            int rank = __popc(m & ((1u << lane) - 1u));
            int base = 0;
            if (lane == __ffs(m) - 1) base = atomicAdd(&g_cnt, __popc(m));
            base = __shfl_sync(0xffffffffu, base, __ffs(m) - 1);
            if (active) g_list[base + rank] = n;
        }
    }

    // w1 = feat @ W_w + b_w : 16 nodes/warp
    __shared__ __align__(16) float Ws[D * D];
    for (int i = threadIdx.x; i < D * D; i += blockDim.x) Ws[i] = Ww[i];
    __syncthreads();
    const float4* Ws4 = reinterpret_cast<const float4*>(Ws);
    int lane = threadIdx.x & 31;
    int sub  = lane & 7;
    int grp  = lane >> 3;
    int warp = tid >> 5;
    int nw   = stride >> 5;
    float4 b4 = __ldg(reinterpret_cast<const float4*>(bw) + sub);
    for (int base = warp * 16; base < n_nodes; base += nw * 16) {
        float4 f4[4], acc[4];
        #pragma unroll
        for (int t = 0; t < 4; t++) {
            int n = base + grp * 4 + t;           // n_nodes % 16 == 0
            f4[t]  = *reinterpret_cast<const float4*>(&feat[n * D + sub * 4]);
            acc[t] = b4;
        }
        #pragma unroll
        for (int k = 0; k < D; k++) {
            float4 w = Ws4[k * 8 + sub];
            #pragma unroll
            for (int t = 0; t < 4; t++) {
                float fk = __shfl_sync(0xffffffffu, fsel(f4[t], k & 3), k >> 2, 8);
                acc[t].x += fk * w.x; acc[t].y += fk * w.y;
                acc[t].z += fk * w.z; acc[t].w += fk * w.w;
            }
        }
        #pragma unroll
        for (int t = 0; t < 4; t++) {
            int n = base + grp * 4 + t;
            *reinterpret_cast<float4*>(&g_w1[n * D + sub * 4]) = acc[t];
        }
    }
}

// ---------------- edge stage: 4 edges/warp, ACTIVE-dst filter, float4, vector RED, unroll 2 ----------------
__global__ void k_edge(const int* __restrict__ src, const int* __restrict__ dst,
                       const int* __restrict__ ety, const float* __restrict__ norm,
                       const float* __restrict__ attn, int nE) {
    __shared__ float4 et_s[NREL * 8];
    for (int i = threadIdx.x; i < NREL * 8; i += blockDim.x)
        et_s[i] = reinterpret_cast<const float4*>(attn)[i];
    __syncthreads();
    int lane = threadIdx.x & 31;
    int sub  = lane & 7;
    int grp  = lane >> 3;
    int warp = (blockIdx.x * blockDim.x + threadIdx.x) >> 5;
    int nw   = (gridDim.x * blockDim.x) >> 5;
    for (int e0 = warp * 8; e0 < nE; e0 += nw * 8) {
        #pragma unroll
        for (int u = 0; u < 2; u++) {
            int e = e0 + u * 4 + grp;
            if (e >= nE) continue;
            int d = __ldg(&dst[e]);
            if (!g_act[d]) continue;              // inactive dst: dead work
            int   s  = __ldg(&src[e]);
            int   r  = __ldg(&ety[e]);
            float nm = __ldg(&norm[e]);
            float4 f = *reinterpret_cast<const float4*>(&g_w1[s * D + sub * 4]);
            float4 t1 = make_float4(nm * f.x, nm * f.y, nm * f.z, nm * f.w);
            red_add_v4(&g_U[d * D + sub * 4], t1);
            float4 et = et_s[r * 8 + sub];
            float4 v  = make_float4(t1.x * et.x, t1.y * et.y, t1.z * et.z, t1.w * et.w);
            red_add_v4(&g_V[d * D + sub * 4], v);
            if (sub == 0) atomicAdd(&g_S[d * 16 + r], nm);
        }
    }
}

// ---------------- combine + scatter over compacted list: 16 nodes/warp ----------------
__global__ void __launch_bounds__(256, 2)
k_nf(const float* __restrict__ feat, const float* __restrict__ bline,
     const int* __restrict__ idx1, const int* __restrict__ idx2,
     const int* __restrict__ f2, const int* __restrict__ tar,
     float* __restrict__ out) {
    __shared__ __align__(16) float M1s[D * D], M2s[D * D], M3s[D * D], Cws[NREL * D];
    for (int i = threadIdx.x; i < D * D; i += blockDim.x) {
        M1s[i] = g_M1[i]; M2s[i] = g_M2[i]; M3s[i] = g_M3[i];
    }
    for (int i = threadIdx.x; i < NREL * D; i += blockDim.x) Cws[i] = g_Cw[i];
    __syncthreads();
    const float4* M14 = reinterpret_cast<const float4*>(M1s);
    const float4* M24 = reinterpret_cast<const float4*>(M2s);
    const float4* M34 = reinterpret_cast<const float4*>(M3s);
    const float4* Cw4 = reinterpret_cast<const float4*>(Cws);
    int cnt  = g_cnt;
    int lane = threadIdx.x & 31;
    int sub  = lane & 7;
    int grp  = lane >> 3;
    int warp = (blockIdx.x * blockDim.x + threadIdx.x) >> 5;
    int nw   = (gridDim.x * blockDim.x) >> 5;
    float4 b4 = __ldg(reinterpret_cast<const float4*>(bline) + sub);

    for (int base = warp * 16; base < cnt; base += nw * 16) {
        int  n_t[4];
        bool val_t[4];
        float4 acc[4];
        #pragma unroll
        for (int t = 0; t < 4; t++) {
            int i = base + grp * 4 + t;
            val_t[t] = i < cnt;
            n_t[t] = g_list[val_t[t] ? i : 0];
            acc[t] = b4;
        }
        {
            float sv0[4], sv1[4];
            #pragma unroll
            for (int t = 0; t < 4; t++) {
                sv0[t] = g_S[n_t[t] * 16 + sub];
                sv1[t] = g_S[n_t[t] * 16 + 8 + sub];
            }
            #pragma unroll
            for (int r = 0; r < NREL; r++) {
                float4 c = Cw4[r * 8 + sub];
                #pragma unroll
                for (int t = 0; t < 4; t++) {
                    float s_r = __shfl_sync(0xffffffffu, r < 8 ? sv0[t] : sv1[t], r & 7, 8);
                    acc[t].x += s_r * c.x; acc[t].y += s_r * c.y;
                    acc[t].z += s_r * c.z; acc[t].w += s_r * c.w;
                }
            }
        }
        {
            float4 u4[4], v4[4], f4[4];
            #pragma unroll
            for (int t = 0; t < 4; t++) {
                u4[t] = *reinterpret_cast<const float4*>(&g_U[n_t[t] * D + sub * 4]);
                v4[t] = *reinterpret_cast<const float4*>(&g_V[n_t[t] * D + sub * 4]);
                f4[t] = *reinterpret_cast<const float4*>(&feat[n_t[t] * D + sub * 4]);
            }
            #pragma unroll
            for (int k = 0; k < D; k++) {
                float4 m1 = M14[k * 8 + sub];
                float4 m2 = M24[k * 8 + sub];
                float4 m3 = M34[k * 8 + sub];
                #pragma unroll
                for (int t = 0; t < 4; t++) {
                    float uk = __shfl_sync(0xffffffffu, fsel(u4[t], k & 3), k >> 2, 8);
                    float vk = __shfl_sync(0xffffffffu, fsel(v4[t], k & 3), k >> 2, 8);
                    float fk = __shfl_sync(0xffffffffu, fsel(f4[t], k & 3), k >> 2, 8);
                    acc[t].x += uk * m1.x + vk * m2.x + fk * m3.x;
                    acc[t].y += uk * m1.y + vk * m2.y + fk * m3.y;
                    acc[t].z += uk * m1.z + vk * m2.z + fk * m3.z;
                    acc[t].w += uk * m1.w + vk * m2.w + fk * m3.w;
                }
            }
        }
        #pragma unroll
        for (int t = 0; t < 4; t++) {
            if (!val_t[t]) continue;
            int n = n_t[t];
            float4 val = make_float4(fmaxf(acc[t].x, 0.f), fmaxf(acc[t].y, 0.f),
                                     fmaxf(acc[t].z, 0.f), fmaxf(acc[t].w, 0.f));
            int b  = n >> 12;                     // n / NPER
            int i1 = __ldg(&idx1[n]);
            int i2 = __ldg(&idx2[n]);
            int tr = __ldg(&tar[n]);
            if (i1 == 1)
                *reinterpret_cast<float4*>(&g_nf[n * D + sub * 4]) = val;
            if (i2 != 0) {
                int slot = __ldg(&f2[n]) + 1;     // index_offset = 1
                if (slot <= NG)                   // slot NG+1 = dump row (dropped)
                    *reinterpret_cast<float4*>(&out[(b * (NG + 1) + slot) * D + sub * 4]) = val;
            }
            if (tr == 1)
                red_add_v4(&out[OUT2_OFF + b * D + sub * 4], val);
        }
    }
}

// ---------------- path softmax phase A: per-sub-block max/sum/partial (SPLIT=8, R=512) ----------------
__global__ void k_path1(const int* __restrict__ idx1, const float* __restrict__ out) {
    const int R = NPER / SPLIT;                   // 512 rows per block
    __shared__ float sc[R];
    __shared__ float tgt[D];
    __shared__ float red[8];
    __shared__ float wacc[8][D];
    int b = blockIdx.x / SPLIT, j = blockIdx.x % SPLIT;
    int t = threadIdx.x;
    int w = t >> 5, lane = t & 31;
    if (t < D) tgt[t] = out[OUT2_OFF + b * D + t];
    __syncthreads();
    size_t rbase = (size_t)b * NPER + (size_t)j * R;

    // scores
    for (int i = t; i < R; i += 256) {
        float s = -1e30f;
        if (idx1[rbase + i] == 1) {
            const float4* row = reinterpret_cast<const float4*>(g_nf + (rbase + i) * D);
            float acc = 0.f;
            #pragma unroll
            for (int k = 0; k < 8; k++) {
                float4 r4 = row[k];
                acc += r4.x * tgt[k * 4 + 0] + r4.y * tgt[k * 4 + 1]
                     + r4.z * tgt[k * 4 + 2] + r4.w * tgt[k * 4 + 3];
            }
            s = acc;
        }
        sc[i] = s;
    }
    __syncthreads();

    // local max
    float m = -1e30f;
    for (int i = t; i < R; i += 256) m = fmaxf(m, sc[i]);
    #pragma unroll
    for (int off = 16; off > 0; off >>= 1)
        m = fmaxf(m, __shfl_xor_sync(0xffffffffu, m, off));
    if (lane == 0) red[w] = m;
    __syncthreads();
    if (t < 8) {
        float mm = red[t];
        #pragma unroll
        for (int off = 4; off > 0; off >>= 1)
            mm = fmaxf(mm, __shfl_xor_sync(0xffu, mm, off));
        red[t] = mm;
    }
    __syncthreads();
    float mloc = red[0];
    __syncthreads();

    if (mloc < -1e29f) {                          // empty sub-block
        if (t == 0) { g_pm[blockIdx.x] = -1e30f; g_ps[blockIdx.x] = 0.f; }
        if (t < D) g_pv[blockIdx.x * D + t] = 0.f;
        return;
    }

    // exp + local sum
    float ssum = 0.f;
    for (int i = t; i < R; i += 256) {
        float e = (sc[i] > -1e29f) ? __expf(sc[i] - mloc) : 0.f;
        sc[i] = e;
        ssum += e;
    }
    #pragma unroll
    for (int off = 16; off > 0; off >>= 1)
        ssum += __shfl_xor_sync(0xffffffffu, ssum, off);
    if (lane == 0) red[w] = ssum;
    __syncthreads();
    if (t < 8) {
        float s2 = red[t];
        #pragma unroll
        for (int off = 4; off > 0; off >>= 1)
            s2 += __shfl_xor_sync(0xffu, s2, off);
        red[t] = s2;
    }
    __syncthreads();
    float sloc = red[0];

    // weighted partial: 8 warps stride rows, lane = dim
    float a = 0.f;
    for (int i = w; i < R; i += 8) {
        float e = sc[i];
        if (e == 0.f) continue;
        a += e * g_nf[(rbase + i) * D + lane];
    }
    wacc[w][lane] = a;
    __syncthreads();
    if (t < D) {
        float acc = 0.f;
        #pragma unroll
        for (int q = 0; q < 8; q++) acc += wacc[q][t];
        g_pv[blockIdx.x * D + t] = acc;
    }
    if (t == 0) { g_pm[blockIdx.x] = mloc; g_ps[blockIdx.x] = sloc; }
}

// ---------------- path softmax phase B: combine + g_cnt reset ----------------
__global__ void k_path2(const float* __restrict__ zero_path, float* __restrict__ out) {
    int b = blockIdx.x, t = threadIdx.x;          // 32 threads
    if (b == 0 && t == 0) g_cnt = 0;              // restore invariant for next call
    float M = -1e30f;
    #pragma unroll
    for (int j = 0; j < SPLIT; j++) M = fmaxf(M, g_pm[b * SPLIT + j]);
    if (M < -1e29f) {
        out[OUT3_OFF + b * D + t] = zero_path[t];
        return;
    }
    float S = 0.f, v = 0.f;
    #pragma unroll
    for (int j = 0; j < SPLIT; j++) {
        float sc = __expf(g_pm[b * SPLIT + j] - M);
        S += sc * g_ps[b * SPLIT + j];
        v += sc * g_pv[(b * SPLIT + j) * D + t];
    }
    out[OUT3_OFF + b * D + t] = v / S;
}

// ---------------- launch ----------------
extern "C" void kernel_launch(void* const* d_in, const int* in_sizes, int n_in,
                              void* d_out, int out_size) {
    const float* feat = (const float*)d_in[0];
    const float* norm = (const float*)d_in[1];
    const float* W_w  = (const float*)d_in[2];
    const float* b_w  = (const float*)d_in[3];
    const float* W2   = (const float*)d_in[4];
    const float* b2   = (const float*)d_in[5];
    const float* attn = (const float*)d_in[6];
    const float* SL   = (const float*)d_in[7];
    const float* Wl   = (const float*)d_in[8];
    const float* bl   = (const float*)d_in[9];
    const float* zp   = (const float*)d_in[10];
    const int*   src  = (const int*)d_in[11];
    const int*   dst  = (const int*)d_in[12];
    const int*   ety  = (const int*)d_in[13];
    const int*   idx1 = (const int*)d_in[14];
    const int*   idx2 = (const int*)d_in[15];
    const int*   f2   = (const int*)d_in[16];
    const int*   tar  = (const int*)d_in[17];

    int nE     = in_sizes[11];
    int nNodes = in_sizes[0] / D;
    float* out = (float*)d_out;

    k_init<<<1184, 256>>>(feat, W_w, b_w, W2, b2, attn, SL, Wl, out,
                          idx1, idx2, tar, nNodes);
    k_edge<<<1184, 256>>>(src, dst, ety, norm, attn, nE);
    k_nf  <<<520, 256>>>(feat, bl, idx1, idx2, f2, tar, out);
    k_path1<<<NBATCH * SPLIT, 256>>>(idx1, out);
    k_path2<<<NBATCH, 32>>>(zp, out);
}

// round 13
// speedup vs baseline: 1.1575x; 1.0561x over previous
#include <cuda_runtime.h>

#define N_NODES 131072
#define NPER    4096
#define NBATCH  32
#define D       32
#define NREL    10
#define NG      14   // num_g_rels
#define SPLIT   8    // path sub-blocks per batch
#define OUT2_OFF (NBATCH * (NG + 1) * D)         // 15360
#define OUT3_OFF (OUT2_OFF + NBATCH * D)         // 16384

// ---------------- scratch (device globals; no allocation allowed) ----------------
__device__ __align__(16) float g_w1[N_NODES * D];
__device__ __align__(16) float g_U [N_NODES * D];    // indexed by COMPACT POSITION
__device__ __align__(16) float g_V [N_NODES * D];    // indexed by COMPACT POSITION
__device__ __align__(16) float g_S [N_NODES * 16];   // indexed by COMPACT POSITION
__device__ __align__(16) float g_nf[N_NODES * D];
__device__ int   g_pos[N_NODES];                 // node -> compact position (-1 inactive)
__device__ int   g_list[N_NODES];                // compact position -> node
__device__ int   g_cnt;                          // invariant: 0 at entry
__device__ float g_M1[D * D];     // (W2a - W2b) @ W_line
__device__ float g_M2[D * D];     // W2c @ W_line
__device__ float g_M3[D * D];     // self_loop_w @ W_line
__device__ float g_Cw[NREL * D];  // (attn_r @ (W2a+W2b) + b2) @ W_line
__device__ float g_pm[NBATCH * SPLIT];
__device__ float g_ps[NBATCH * SPLIT];
__device__ __align__(16) float g_pv[NBATCH * SPLIT * D];

__device__ __forceinline__ void red_add_v4(float* p, float4 v) {
    asm volatile("red.global.add.v4.f32 [%0], {%1,%2,%3,%4};"
                 :: "l"(p), "f"(v.x), "f"(v.y), "f"(v.z), "f"(v.w) : "memory");
}
__device__ __forceinline__ float fsel(const float4& q, int c) {
    return c == 0 ? q.x : (c == 1 ? q.y : (c == 2 ? q.z : q.w));
}

// ---------------- init: prep (block 0) + zero out + compaction/pos (+row zero) + w1 ----------------
__global__ void k_init(const float* __restrict__ feat, const float* __restrict__ Ww,
                       const float* __restrict__ bw,
                       const float* __restrict__ W2, const float* __restrict__ b2,
                       const float* __restrict__ attn, const float* __restrict__ SL,
                       const float* __restrict__ Wl,
                       float* __restrict__ out,
                       const int* __restrict__ idx1, const int* __restrict__ idx2,
                       const int* __restrict__ tar, int n_nodes) {
    if (blockIdx.x == 0) {
        __shared__ float Cs[NREL * D];
        int t = threadIdx.x;
        for (int i = t; i < NREL * D; i += blockDim.x) {
            int r = i / D, j = i % D;
            float acc = b2[j];
            #pragma unroll
            for (int k = 0; k < D; k++)
                acc += attn[r * D + k] * (W2[k * D + j] + W2[(D + k) * D + j]);
            Cs[i] = acc;
        }
        __syncthreads();
        for (int i = t; i < D * D; i += blockDim.x) {
            int k = i / D, d = i % D;
            float m1 = 0.f, m2 = 0.f, m3 = 0.f;
            #pragma unroll
            for (int j = 0; j < D; j++) {
                float wl = Wl[j * D + d];
                m1 += (W2[k * D + j] - W2[(D + k) * D + j]) * wl;
                m2 += W2[(2 * D + k) * D + j] * wl;
                m3 += SL[k * D + j] * wl;
            }
            g_M1[i] = m1; g_M2[i] = m2; g_M3[i] = m3;
        }
        for (int i = t; i < NREL * D; i += blockDim.x) {
            int r = i / D, d = i % D;
            float acc = 0.f;
            #pragma unroll
            for (int j = 0; j < D; j++) acc += Cs[r * D + j] * Wl[j * D + d];
            g_Cw[i] = acc;
        }
    }

    int tid = blockIdx.x * blockDim.x + threadIdx.x;
    int stride = gridDim.x * blockDim.x;
    if (tid < OUT3_OFF) out[tid] = 0.f;

    // compaction + position map + zero the claimed U/V/S rows (g_cnt == 0 at entry).
    // Positions within a warp are dense, so the zero-stores cover contiguous regions.
    {
        int n = tid;                              // stride >= n_nodes
        bool active = false;
        if (n < n_nodes)
            active = (__ldg(&idx1[n]) == 1) || (__ldg(&idx2[n]) != 0) || (__ldg(&tar[n]) == 1);
        unsigned m = __ballot_sync(0xffffffffu, active);
        int pos = -1;
        if (m) {
            int lane = threadIdx.x & 31;
            int rank = __popc(m & ((1u << lane) - 1u));
            int base = 0;
            if (lane == __ffs(m) - 1) base = atomicAdd(&g_cnt, __popc(m));
            base = __shfl_sync(0xffffffffu, base, __ffs(m) - 1);
            if (active) pos = base + rank;
        }
        if (n < n_nodes) g_pos[n] = pos;
        if (pos >= 0) {
            g_list[pos] = n;
            float4 z = make_float4(0.f, 0.f, 0.f, 0.f);
            float4* U4 = reinterpret_cast<float4*>(g_U) + pos * 8;
            float4* V4 = reinterpret_cast<float4*>(g_V) + pos * 8;
            float4* S4 = reinterpret_cast<float4*>(g_S) + pos * 4;
            #pragma unroll
            for (int j = 0; j < 8; j++) { U4[j] = z; V4[j] = z; }
            #pragma unroll
            for (int j = 0; j < 4; j++) S4[j] = z;
        }
    }

    // w1 = feat @ W_w + b_w : 16 nodes/warp
    __shared__ __align__(16) float Ws[D * D];
    for (int i = threadIdx.x; i < D * D; i += blockDim.x) Ws[i] = Ww[i];
    __syncthreads();
    const float4* Ws4 = reinterpret_cast<const float4*>(Ws);
    int lane = threadIdx.x & 31;
    int sub  = lane & 7;
    int grp  = lane >> 3;
    int warp = tid >> 5;
    int nw   = stride >> 5;
    float4 b4 = __ldg(reinterpret_cast<const float4*>(bw) + sub);
    for (int base = warp * 16; base < n_nodes; base += nw * 16) {
        float4 f4[4], acc[4];
        #pragma unroll
        for (int t = 0; t < 4; t++) {
            int n = base + grp * 4 + t;           // n_nodes % 16 == 0
            f4[t]  = *reinterpret_cast<const float4*>(&feat[n * D + sub * 4]);
            acc[t] = b4;
        }
        #pragma unroll
        for (int k = 0; k < D; k++) {
            float4 w = Ws4[k * 8 + sub];
            #pragma unroll
            for (int t = 0; t < 4; t++) {
                float fk = __shfl_sync(0xffffffffu, fsel(f4[t], k & 3), k >> 2, 8);
                acc[t].x += fk * w.x; acc[t].y += fk * w.y;
                acc[t].z += fk * w.z; acc[t].w += fk * w.w;
            }
        }
        #pragma unroll
        for (int t = 0; t < 4; t++) {
            int n = base + grp * 4 + t;
            *reinterpret_cast<float4*>(&g_w1[n * D + sub * 4]) = acc[t];
        }
    }
}

// ---------------- edge stage: 4 edges/warp, position-indexed accumulators ----------------
__global__ void k_edge(const int* __restrict__ src, const int* __restrict__ dst,
                       const int* __restrict__ ety, const float* __restrict__ norm,
                       const float* __restrict__ attn, int nE) {
    __shared__ float4 et_s[NREL * 8];
    for (int i = threadIdx.x; i < NREL * 8; i += blockDim.x)
        et_s[i] = reinterpret_cast<const float4*>(attn)[i];
    __syncthreads();
    int lane = threadIdx.x & 31;
    int sub  = lane & 7;
    int grp  = lane >> 3;
    int warp = (blockIdx.x * blockDim.x + threadIdx.x) >> 5;
    int nw   = (gridDim.x * blockDim.x) >> 5;
    for (int e0 = warp * 8; e0 < nE; e0 += nw * 8) {
        #pragma unroll
        for (int u = 0; u < 2; u++) {
            int e = e0 + u * 4 + grp;
            if (e >= nE) continue;
            int d = __ldg(&dst[e]);
            int p = __ldg(&g_pos[d]);
            if (p < 0) continue;                  // inactive dst: dead work
            int   s  = __ldg(&src[e]);
            int   r  = __ldg(&ety[e]);
            float nm = __ldg(&norm[e]);
            float4 f = *reinterpret_cast<const float4*>(&g_w1[s * D + sub * 4]);
            float4 t1 = make_float4(nm * f.x, nm * f.y, nm * f.z, nm * f.w);
            red_add_v4(&g_U[p * D + sub * 4], t1);
            float4 et = et_s[r * 8 + sub];
            float4 v  = make_float4(t1.x * et.x, t1.y * et.y, t1.z * et.z, t1.w * et.w);
            red_add_v4(&g_V[p * D + sub * 4], v);
            if (sub == 0) atomicAdd(&g_S[p * 16 + r], nm);
        }
    }
}

// ---------------- combine + scatter: U/V/S read SEQUENTIALLY by position ----------------
__global__ void __launch_bounds__(256, 2)
k_nf(const float* __restrict__ feat, const float* __restrict__ bline,
     const int* __restrict__ idx1, const int* __restrict__ idx2,
     const int* __restrict__ f2, const int* __restrict__ tar,
     float* __restrict__ out) {
    __shared__ __align__(16) float M1s[D * D], M2s[D * D], M3s[D * D], Cws[NREL * D];
    for (int i = threadIdx.x; i < D * D; i += blockDim.x) {
        M1s[i] = g_M1[i]; M2s[i] = g_M2[i]; M3s[i] = g_M3[i];
    }
    for (int i = threadIdx.x; i < NREL * D; i += blockDim.x) Cws[i] = g_Cw[i];
    __syncthreads();
    const float4* M14 = reinterpret_cast<const float4*>(M1s);
    const float4* M24 = reinterpret_cast<const float4*>(M2s);
    const float4* M34 = reinterpret_cast<const float4*>(M3s);
    const float4* Cw4 = reinterpret_cast<const float4*>(Cws);
    int cnt  = g_cnt;
    int lane = threadIdx.x & 31;
    int sub  = lane & 7;
    int grp  = lane >> 3;
    int warp = (blockIdx.x * blockDim.x + threadIdx.x) >> 5;
    int nw   = (gridDim.x * blockDim.x) >> 5;
    float4 b4 = __ldg(reinterpret_cast<const float4*>(bline) + sub);

    for (int base = warp * 16; base < cnt; base += nw * 16) {
        int  i_t[4], n_t[4];
        bool val_t[4];
        float4 acc[4];
        #pragma unroll
        for (int t = 0; t < 4; t++) {
            int i = base + grp * 4 + t;
            val_t[t] = i < cnt;
            i_t[t] = val_t[t] ? i : 0;
            n_t[t] = g_list[i_t[t]];
            acc[t] = b4;
        }
        {
            float sv0[4], sv1[4];
            #pragma unroll
            for (int t = 0; t < 4; t++) {
                sv0[t] = g_S[i_t[t] * 16 + sub];
                sv1[t] = g_S[i_t[t] * 16 + 8 + sub];
            }
            #pragma unroll
            for (int r = 0; r < NREL; r++) {
                float4 c = Cw4[r * 8 + sub];
                #pragma unroll
                for (int t = 0; t < 4; t++) {
                    float s_r = __shfl_sync(0xffffffffu, r < 8 ? sv0[t] : sv1[t], r & 7, 8);
                    acc[t].x += s_r * c.x; acc[t].y += s_r * c.y;
                    acc[t].z += s_r * c.z; acc[t].w += s_r * c.w;
                }
            }
        }
        {
            float4 u4[4], v4[4], f4[4];
            #pragma unroll
            for (int t = 0; t < 4; t++) {
                u4[t] = *reinterpret_cast<const float4*>(&g_U[i_t[t] * D + sub * 4]);
                v4[t] = *reinterpret_cast<const float4*>(&g_V[i_t[t] * D + sub * 4]);
                f4[t] = *reinterpret_cast<const float4*>(&feat[n_t[t] * D + sub * 4]);
            }
            #pragma unroll
            for (int k = 0; k < D; k++) {
                float4 m1 = M14[k * 8 + sub];
                float4 m2 = M24[k * 8 + sub];
                float4 m3 = M34[k * 8 + sub];
                #pragma unroll
                for (int t = 0; t < 4; t++) {
                    float uk = __shfl_sync(0xffffffffu, fsel(u4[t], k & 3), k >> 2, 8);
                    float vk = __shfl_sync(0xffffffffu, fsel(v4[t], k & 3), k >> 2, 8);
                    float fk = __shfl_sync(0xffffffffu, fsel(f4[t], k & 3), k >> 2, 8);
                    acc[t].x += uk * m1.x + vk * m2.x + fk * m3.x;
                    acc[t].y += uk * m1.y + vk * m2.y + fk * m3.y;
                    acc[t].z += uk * m1.z + vk * m2.z + fk * m3.z;
                    acc[t].w += uk * m1.w + vk * m2.w + fk * m3.w;
                }
            }
        }
        #pragma unroll
        for (int t = 0; t < 4; t++) {
            if (!val_t[t]) continue;
            int n = n_t[t];
            float4 val = make_float4(fmaxf(acc[t].x, 0.f), fmaxf(acc[t].y, 0.f),
                                     fmaxf(acc[t].z, 0.f), fmaxf(acc[t].w, 0.f));
            int b  = n >> 12;                     // n / NPER
            int i1 = __ldg(&idx1[n]);
            int i2 = __ldg(&idx2[n]);
            int tr = __ldg(&tar[n]);
            if (i1 == 1)
                *reinterpret_cast<float4*>(&g_nf[n * D + sub * 4]) = val;
            if (i2 != 0) {
                int slot = __ldg(&f2[n]) + 1;     // index_offset = 1
                if (slot <= NG)                   // slot NG+1 = dump row (dropped)
                    *reinterpret_cast<float4*>(&out[(b * (NG + 1) + slot) * D + sub * 4]) = val;
            }
            if (tr == 1)
                red_add_v4(&out[OUT2_OFF + b * D + sub * 4], val);
        }
    }
}

// ---------------- path softmax phase A: per-sub-block max/sum/partial (SPLIT=8, R=512) ----------------
__global__ void k_path1(const int* __restrict__ idx1, const float* __restrict__ out) {
    const int R = NPER / SPLIT;                   // 512 rows per block
    __shared__ float sc[R];
    __shared__ float tgt[D];
    __shared__ float red[8];
    __shared__ float wacc[8][D];
    int b = blockIdx.x / SPLIT, j = blockIdx.x % SPLIT;
    int t = threadIdx.x;
    int w = t >> 5, lane = t & 31;
    if (t < D) tgt[t] = out[OUT2_OFF + b * D + t];
    __syncthreads();
    size_t rbase = (size_t)b * NPER + (size_t)j * R;

    for (int i = t; i < R; i += 256) {
        float s = -1e30f;
        if (idx1[rbase + i] == 1) {
            const float4* row = reinterpret_cast<const float4*>(g_nf + (rbase + i) * D);
            float acc = 0.f;
            #pragma unroll
            for (int k = 0; k < 8; k++) {
                float4 r4 = row[k];
                acc += r4.x * tgt[k * 4 + 0] + r4.y * tgt[k * 4 + 1]
                     + r4.z * tgt[k * 4 + 2] + r4.w * tgt[k * 4 + 3];
            }
            s = acc;
        }
        sc[i] = s;
    }
    __syncthreads();

    float m = -1e30f;
    for (int i = t; i < R; i += 256) m = fmaxf(m, sc[i]);
    #pragma unroll
    for (int off = 16; off > 0; off >>= 1)
        m = fmaxf(m, __shfl_xor_sync(0xffffffffu, m, off));
    if (lane == 0) red[w] = m;
    __syncthreads();
    if (t < 8) {
        float mm = red[t];
        #pragma unroll
        for (int off = 4; off > 0; off >>= 1)
            mm = fmaxf(mm, __shfl_xor_sync(0xffu, mm, off));
        red[t] = mm;
    }
    __syncthreads();
    float mloc = red[0];
    __syncthreads();

    if (mloc < -1e29f) {                          // empty sub-block
        if (t == 0) { g_pm[blockIdx.x] = -1e30f; g_ps[blockIdx.x] = 0.f; }
        if (t < D) g_pv[blockIdx.x * D + t] = 0.f;
        return;
    }

    float ssum = 0.f;
    for (int i = t; i < R; i += 256) {
        float e = (sc[i] > -1e29f) ? __expf(sc[i] - mloc) : 0.f;
        sc[i] = e;
        ssum += e;
    }
    #pragma unroll
    for (int off = 16; off > 0; off >>= 1)
        ssum += __shfl_xor_sync(0xffffffffu, ssum, off);
    if (lane == 0) red[w] = ssum;
    __syncthreads();
    if (t < 8) {
        float s2 = red[t];
        #pragma unroll
        for (int off = 4; off > 0; off >>= 1)
            s2 += __shfl_xor_sync(0xffu, s2, off);
        red[t] = s2;
    }
    __syncthreads();
    float sloc = red[0];

    float a = 0.f;
    for (int i = w; i < R; i += 8) {
        float e = sc[i];
        if (e == 0.f) continue;
        a += e * g_nf[(rbase + i) * D + lane];
    }
    wacc[w][lane] = a;
    __syncthreads();
    if (t < D) {
        float acc = 0.f;
        #pragma unroll
        for (int q = 0; q < 8; q++) acc += wacc[q][t];
        g_pv[blockIdx.x * D + t] = acc;
    }
    if (t == 0) { g_pm[blockIdx.x] = mloc; g_ps[blockIdx.x] = sloc; }
}

// ---------------- path softmax phase B: combine + g_cnt reset ----------------
__global__ void k_path2(const float* __restrict__ zero_path, float* __restrict__ out) {
    int b = blockIdx.x, t = threadIdx.x;          // 32 threads
    if (b == 0 && t == 0) g_cnt = 0;              // restore invariant for next call
    float M = -1e30f;
    #pragma unroll
    for (int j = 0; j < SPLIT; j++) M = fmaxf(M, g_pm[b * SPLIT + j]);
    if (M < -1e29f) {
        out[OUT3_OFF + b * D + t] = zero_path[t];
        return;
    }
    float S = 0.f, v = 0.f;
    #pragma unroll
    for (int j = 0; j < SPLIT; j++) {
        float sc = __expf(g_pm[b * SPLIT + j] - M);
        S += sc * g_ps[b * SPLIT + j];
        v += sc * g_pv[(b * SPLIT + j) * D + t];
    }
    out[OUT3_OFF + b * D + t] = v / S;
}

// ---------------- launch ----------------
extern "C" void kernel_launch(void* const* d_in, const int* in_sizes, int n_in,
                              void* d_out, int out_size) {
    const float* feat = (const float*)d_in[0];
    const float* norm = (const float*)d_in[1];
    const float* W_w  = (const float*)d_in[2];
    const float* b_w  = (const float*)d_in[3];
    const float* W2   = (const float*)d_in[4];
    const float* b2   = (const float*)d_in[5];
    const float* attn = (const float*)d_in[6];
    const float* SL   = (const float*)d_in[7];
    const float* Wl   = (const float*)d_in[8];
    const float* bl   = (const float*)d_in[9];
    const float* zp   = (const float*)d_in[10];
    const int*   src  = (const int*)d_in[11];
    const int*   dst  = (const int*)d_in[12];
    const int*   ety  = (const int*)d_in[13];
    const int*   idx1 = (const int*)d_in[14];
    const int*   idx2 = (const int*)d_in[15];
    const int*   f2   = (const int*)d_in[16];
    const int*   tar  = (const int*)d_in[17];

    int nE     = in_sizes[11];
    int nNodes = in_sizes[0] / D;
    float* out = (float*)d_out;

    k_init<<<1184, 256>>>(feat, W_w, b_w, W2, b2, attn, SL, Wl, out,
                          idx1, idx2, tar, nNodes);
    k_edge<<<1184, 256>>>(src, dst, ety, norm, attn, nE);
    k_nf  <<<520, 256>>>(feat, bl, idx1, idx2, f2, tar, out);
    k_path1<<<NBATCH * SPLIT, 256>>>(idx1, out);
    k_path2<<<NBATCH, 32>>>(zp, out);
}